// round 16
// baseline (speedup 1.0000x reference)
#include <cuda_runtime.h>

// Problem shapes (fixed by the reference)
#define MDIM 16384
#define NDIM 16384
#define BC   8            // B * C_IN = 2*4
#define CHUNK 1024        // m-chunk staged in shared: 8 * 1024 * 4B = 32 KB
#define NCHUNK (MDIM / CHUNK)            // 16
#define IPC   (CHUNK / 128)              // 8 iterations per chunk (128 floats/iter)
#define NITER (NCHUNK * IPC)             // 128 flat iterations
#define ROWS_PER_BLOCK 16
#define THREADS 128       // 4 warps; each warp owns 4 rows
#define NTILES (NDIM / ROWS_PER_BLOCK)   // 1024 row-tiles
#define NSM    148
#define BLKSM  6
#define GRID   (NSM * BLKSM)             // 888 persistent blocks

// y[b,o,n] = sum_c theta[o,c] * (sum_m D[n,m] x[b,c,m]) + bias[o]
//
// Persistent single-wave launch: 888 blocks (6/SM), grid-striding over 1024
// row-tiles (136 blocks do 2 tiles; spread ~evenly across SMs -> ~1% tail).
// D is streamed with a depth-1 register prefetch pipeline: the next
// iteration's 4 LDG.128 are in flight during the current iteration's FMA
// chain AND across the per-chunk staging barriers, doubling in-flight DRAM
// bytes per warp (Little's-law fix for the 73% DRAM plateau).
__global__ __launch_bounds__(THREADS, BLKSM)
void coboundary_kernel(const float* __restrict__ D,
                       const float* __restrict__ x,      // [8][MDIM]
                       const float* __restrict__ theta,  // [8][4]
                       const float* __restrict__ bias,   // [8]
                       float* __restrict__ out)          // [16][NDIM]
{
    __shared__ float sx[BC][CHUNK];

    const int tid = threadIdx.x;
    const int tx  = tid & 31;        // lane
    const int ty  = tid >> 5;        // warp 0..3

    for (int tile = blockIdx.x; tile < NTILES; tile += GRID) {
        const int row0 = tile * ROWS_PER_BLOCK + ty * 4;
        const float* __restrict__ Drow = D + (size_t)row0 * MDIM + tx * 4;

        float acc[4][BC];
#pragma unroll
        for (int r = 0; r < 4; ++r)
#pragma unroll
            for (int c = 0; c < BC; ++c) acc[r][c] = 0.0f;

        // Prime the D pipeline: loads for flat iteration 0.
        float4 dc[4];
#pragma unroll
        for (int r = 0; r < 4; ++r)
            dc[r] = __ldcs(reinterpret_cast<const float4*>(
                Drow + (size_t)r * MDIM));

        for (int c = 0; c < NCHUNK; ++c) {
            __syncthreads();   // previous chunk's readers done
            // Stage the x chunk: 256 float4/channel, 2 per thread per channel.
#pragma unroll
            for (int bc = 0; bc < BC; ++bc) {
                const float4* src = reinterpret_cast<const float4*>(
                    x + (size_t)bc * MDIM + c * CHUNK);
                float4* dst = reinterpret_cast<float4*>(&sx[bc][0]);
                dst[tid]       = src[tid];
                dst[tid + 128] = src[tid + 128];
            }
            __syncthreads();

#pragma unroll
            for (int i = 0; i < IPC; ++i) {
                const int it = c * IPC + i;
                // Prefetch next flat iteration's D rows (stays in flight
                // through this iteration's FMAs and the next barrier).
                const int mnext = (it < NITER - 1) ? (it + 1) * 128 : it * 128;
                float4 dn[4];
#pragma unroll
                for (int r = 0; r < 4; ++r)
                    dn[r] = __ldcs(reinterpret_cast<const float4*>(
                        Drow + (size_t)r * MDIM + mnext));

                const int mo = i * 128 + tx * 4;
#pragma unroll
                for (int bc = 0; bc < BC; ++bc) {
                    const float4 xs =
                        *reinterpret_cast<const float4*>(&sx[bc][mo]);
#pragma unroll
                    for (int r = 0; r < 4; ++r) {
                        acc[r][bc] = fmaf(dc[r].x, xs.x, acc[r][bc]);
                        acc[r][bc] = fmaf(dc[r].y, xs.y, acc[r][bc]);
                        acc[r][bc] = fmaf(dc[r].z, xs.z, acc[r][bc]);
                        acc[r][bc] = fmaf(dc[r].w, xs.w, acc[r][bc]);
                    }
                }
#pragma unroll
                for (int r = 0; r < 4; ++r) dc[r] = dn[r];
            }
        }

        // Butterfly reduction: every lane ends with the full row sums.
#pragma unroll
        for (int r = 0; r < 4; ++r)
#pragma unroll
            for (int c = 0; c < BC; ++c)
#pragma unroll
                for (int off = 16; off > 0; off >>= 1)
                    acc[r][c] += __shfl_xor_sync(0xffffffffu, acc[r][c], off);

        // Epilogue: fold theta + bias. Warp owns 4 rows * 16 (b,o) = 64
        // outputs; each lane writes 2.
        const int r = tx >> 3;        // 0..3
        const int k = tx & 7;         // 0..7
        const int n = row0 + r;
#pragma unroll
        for (int t = 0; t < 2; ++t) {
            const int bo = k + t * 8;     // 0..15
            const int b  = bo >> 3;
            const int o  = bo & 7;
            const float4 th = *reinterpret_cast<const float4*>(&theta[o * 4]);
            float y = bias[o];
            y = fmaf(th.x, acc[r][b * 4 + 0], y);
            y = fmaf(th.y, acc[r][b * 4 + 1], y);
            y = fmaf(th.z, acc[r][b * 4 + 2], y);
            y = fmaf(th.w, acc[r][b * 4 + 3], y);
            out[(size_t)bo * NDIM + n] = y;
        }
        __syncthreads();   // keep sx stable until all warps finished the tile
    }
}

extern "C" void kernel_launch(void* const* d_in, const int* in_sizes, int n_in,
                              void* d_out, int out_size)
{
    const float* D     = (const float*)d_in[0];   // [16384,16384]
    const float* x     = (const float*)d_in[1];   // [2,4,16384]
    const float* theta = (const float*)d_in[2];   // [8,4]
    const float* bias  = (const float*)d_in[3];   // [1,8,1] -> 8 floats
    float* out = (float*)d_out;                   // [2,8,16384]

    coboundary_kernel<<<GRID, THREADS>>>(D, x, theta, bias, out);
}

// round 17
// speedup vs baseline: 1.5349x; 1.5349x over previous
#include <cuda_runtime.h>

// Problem shapes (fixed by the reference)
#define MDIM 16384
#define NDIM 16384
#define BC   8            // B * C_IN = 2*4
#define ROWS_PER_BLOCK 16
#define THREADS 128       // 4 warps; each warp owns 4 rows
#define NITER (MDIM / 128)   // 128 iterations, 128 floats of m per iteration

// y[b,o,n] = sum_c theta[o,c] * (sum_m D[n,m] x[b,c,m]) + bias[o]
//
// Barrier-free design: x is read directly through L1 (no shared staging, no
// __syncthreads in the main loop). All 28 warps/SM sweep the same x slice at
// the same rate, so x LDGs are ~28x L1-reused. Warps destagger naturally,
// keeping D loads continuously in flight (fixes the 73% DRAM lockstep
// plateau seen with every barrier-based staging scheme).
__global__ __launch_bounds__(THREADS, 7)
void coboundary_kernel(const float* __restrict__ D,
                       const float* __restrict__ x,      // [8][MDIM]
                       const float* __restrict__ theta,  // [8][4]
                       const float* __restrict__ bias,   // [8]
                       float* __restrict__ out)          // [16][NDIM]
{
    const int tid = threadIdx.x;
    const int tx  = tid & 31;        // lane
    const int ty  = tid >> 5;        // warp 0..3
    const int row0 = blockIdx.x * ROWS_PER_BLOCK + ty * 4;

    float acc[4][BC];
#pragma unroll
    for (int r = 0; r < 4; ++r)
#pragma unroll
        for (int c = 0; c < BC; ++c) acc[r][c] = 0.0f;

    // Per-lane base pointers (lane covers 16B at mo = it*128 + tx*4)
    const float* __restrict__ Dbase = D + (size_t)row0 * MDIM + tx * 4;
    const float* __restrict__ xbase = x + tx * 4;

#pragma unroll 2
    for (int it = 0; it < NITER; ++it) {
        const int mo = it * 128;

        // 4 coalesced streaming loads of D (zero reuse -> evict-first)
        float4 d[4];
#pragma unroll
        for (int r = 0; r < 4; ++r)
            d[r] = __ldcs(reinterpret_cast<const float4*>(
                Dbase + (size_t)r * MDIM + mo));

        // 8 channel slices of x straight from L1 (heavily reused across
        // warps/blocks on the same SM). One live at a time keeps regs <= 73.
#pragma unroll
        for (int bc = 0; bc < BC; ++bc) {
            const float4 xs = __ldg(reinterpret_cast<const float4*>(
                xbase + (size_t)bc * MDIM + mo));
#pragma unroll
            for (int r = 0; r < 4; ++r) {
                acc[r][bc] = fmaf(d[r].x, xs.x, acc[r][bc]);
                acc[r][bc] = fmaf(d[r].y, xs.y, acc[r][bc]);
                acc[r][bc] = fmaf(d[r].z, xs.z, acc[r][bc]);
                acc[r][bc] = fmaf(d[r].w, xs.w, acc[r][bc]);
            }
        }
    }

    // Butterfly reduction: every lane ends with the full row sums.
#pragma unroll
    for (int r = 0; r < 4; ++r)
#pragma unroll
        for (int c = 0; c < BC; ++c)
#pragma unroll
            for (int off = 16; off > 0; off >>= 1)
                acc[r][c] += __shfl_xor_sync(0xffffffffu, acc[r][c], off);

    // Epilogue: fold theta + bias. Warp owns 4 rows * 16 (b,o) = 64 outputs;
    // each lane writes 2.
    const int r = tx >> 3;        // 0..3
    const int k = tx & 7;         // 0..7
    const int n = row0 + r;
#pragma unroll
    for (int t = 0; t < 2; ++t) {
        const int bo = k + t * 8;     // 0..15
        const int b  = bo >> 3;
        const int o  = bo & 7;
        const float4 th = *reinterpret_cast<const float4*>(&theta[o * 4]);
        float y = bias[o];
        y = fmaf(th.x, acc[r][b * 4 + 0], y);
        y = fmaf(th.y, acc[r][b * 4 + 1], y);
        y = fmaf(th.z, acc[r][b * 4 + 2], y);
        y = fmaf(th.w, acc[r][b * 4 + 3], y);
        out[(size_t)bo * NDIM + n] = y;
    }
}

extern "C" void kernel_launch(void* const* d_in, const int* in_sizes, int n_in,
                              void* d_out, int out_size)
{
    const float* D     = (const float*)d_in[0];   // [16384,16384]
    const float* x     = (const float*)d_in[1];   // [2,4,16384]
    const float* theta = (const float*)d_in[2];   // [8,4]
    const float* bias  = (const float*)d_in[3];   // [1,8,1] -> 8 floats
    float* out = (float*)d_out;                   // [2,8,16384]

    const int blocks = NDIM / ROWS_PER_BLOCK;     // 1024 = single wave @ 7/SM
    coboundary_kernel<<<blocks, THREADS>>>(D, x, theta, bias, out);
}